// round 10
// baseline (speedup 1.0000x reference)
#include <cuda_runtime.h>
#include <cstdint>

#define D 4096
#define T 64
#define OCC 6
#define ROW_BYTES (D * 4)

// ---------------- mbarrier + TMA bulk helpers (verified R9) ----------------
__device__ __forceinline__ uint32_t smem_u32(const void* p) {
    uint32_t a;
    asm("{ .reg .u64 t; cvta.to.shared.u64 t, %1; cvt.u32.u64 %0, t; }"
        : "=r"(a) : "l"(p));
    return a;
}
__device__ __forceinline__ void mbar_init(uint32_t mbar, uint32_t cnt) {
    asm volatile("mbarrier.init.shared.b64 [%0], %1;" :: "r"(mbar), "r"(cnt) : "memory");
}
__device__ __forceinline__ void mbar_expect_tx(uint32_t mbar, uint32_t bytes) {
    asm volatile("mbarrier.arrive.expect_tx.shared.b64 _, [%0], %1;"
                 :: "r"(mbar), "r"(bytes) : "memory");
}
__device__ __forceinline__ void bulk_g2s(uint32_t dst, const void* src,
                                         uint32_t bytes, uint32_t mbar) {
    asm volatile("cp.async.bulk.shared::cta.global.mbarrier::complete_tx::bytes "
                 "[%0], [%1], %2, [%3];"
                 :: "r"(dst), "l"(src), "r"(bytes), "r"(mbar) : "memory");
}
__device__ __forceinline__ void mbar_wait(uint32_t mbar, uint32_t parity) {
    asm volatile(
        "{\n\t"
        ".reg .pred P;\n\t"
        "WAIT_%=:\n\t"
        "mbarrier.try_wait.parity.acquire.cta.shared::cta.b64 P, [%0], %1, 0x989680;\n\t"
        "@P bra.uni DONE_%=;\n\t"
        "bra.uni WAIT_%=;\n\t"
        "DONE_%=:\n\t"
        "}" :: "r"(mbar), "r"(parity) : "memory");
}

// ---------------- packed f32x2 math (verified R6) ----------------
__device__ __forceinline__ void bfly2(float& a0, float& a1, float& b0, float& b1) {
    asm("{\n\t"
        ".reg .b32 m;\n\t"
        ".reg .b64 ra, rb, rs, rd, rn;\n\t"
        "mov.b32 m, 0xBF800000;\n\t"
        "mov.b64 rn, {m, m};\n\t"
        "mov.b64 ra, {%0, %1};\n\t"
        "mov.b64 rb, {%2, %3};\n\t"
        "add.rn.f32x2 rs, ra, rb;\n\t"
        "fma.rn.f32x2 rd, rb, rn, ra;\n\t"
        "mov.b64 {%0, %1}, rs;\n\t"
        "mov.b64 {%2, %3}, rd;\n\t"
        "}" : "+f"(a0), "+f"(a1), "+f"(b0), "+f"(b1));
}
__device__ __forceinline__ void scale2(float& a0, float& a1, float c) {
    asm("{\n\t"
        ".reg .b64 ra, rs, rm;\n\t"
        "mov.b64 ra, {%0, %1};\n\t"
        "mov.b64 rs, {%2, %2};\n\t"
        "mul.rn.f32x2 rm, ra, rs;\n\t"
        "mov.b64 {%0, %1}, rm;\n\t"
        "}" : "+f"(a0), "+f"(a1) : "f"(c));
}

// 64-point FWHT over reg-index bits 0..5; bits 1..5 packed (pairs along bit 0),
// bit 0 scalar. Stages commute.
__device__ __forceinline__ void fwht64p(float r[64]) {
#pragma unroll
    for (int h = 1; h < 32; h <<= 1) {      // pair-index bits = reg bits 1..5
#pragma unroll
        for (int p = 0; p < 32; p++) {
            if (!(p & h)) {
                bfly2(r[2 * p], r[2 * p + 1],
                      r[2 * (p | h)], r[2 * (p | h) + 1]);
            }
        }
    }
#pragma unroll
    for (int p = 0; p < 32; p++) {          // reg bit 0
        float a = r[2 * p], b = r[2 * p + 1];
        r[2 * p]     = a + b;
        r[2 * p + 1] = a - b;
    }
}

// Swizzle: phys(f) = f ^ (((f>>6)&31)<<2). Bijection on [0,4096).
//   A-write (f = t | m<<6): addr = t ^ (m<<6) ^ ((m&31)<<2)
//     wavefront: m fixed, lanes t -> bank = t&31 ^ const  (conflict-free)
//   C-read float4 (f = w | v<<6): addr4 = q ^ (v<<4) ^ (v&31), q=w>>2
//     per 8-lane phase: addr4&7 = (q^v)&7 distinct       (conflict-free)
//   A-read raw linear (f = t + m*64): bank = t&31          (conflict-free)

__global__ __launch_bounds__(T, OCC)
void rht_kernel(const float* __restrict__ x,
                const float* __restrict__ signs,
                float* __restrict__ out,
                int n_rows, int stride) {
    __shared__ __align__(16) float stage[2][D];
    __shared__ __align__(8)  unsigned long long mbar[2];

    const int t = threadIdx.x;   // 0..63

    const uint32_t st32[2] = { smem_u32(&stage[0][0]), smem_u32(&stage[1][0]) };
    const uint32_t mb32[2] = { smem_u32(&mbar[0]),     smem_u32(&mbar[1])     };

    // sign bitmasks: bit m = signbit(signs[t + m*64])   (signs are exactly +/-1)
    unsigned sm0 = 0, sm1 = 0;
#pragma unroll
    for (int m = 0; m < 32; m++) {
        sm0 |= (__float_as_uint(signs[t + (m << 6)]) >> 31) << m;
    }
#pragma unroll
    for (int m = 32; m < 64; m++) {
        sm1 |= (__float_as_uint(signs[t + (m << 6)]) >> 31) << (m - 32);
    }

    if (t == 0) {
        mbar_init(mb32[0], 1);
        mbar_init(mb32[1], 1);
    }
    __syncthreads();

    int row = blockIdx.x;

    // prologue: buf0 <- row, buf1 <- row+stride
    if (t == 0) {
        mbar_expect_tx(mb32[0], ROW_BYTES);
        bulk_g2s(st32[0], x + (size_t)row * D, ROW_BYTES, mb32[0]);
        const int r1 = row + stride;
        if (r1 < n_rows) {
            mbar_expect_tx(mb32[1], ROW_BYTES);
            bulk_g2s(st32[1], x + (size_t)r1 * D, ROW_BYTES, mb32[1]);
        }
    }

    int bq = 0;
    unsigned ph[2] = { 0, 0 };

    while (row < n_rows) {
        mbar_wait(mb32[bq], ph[bq]);   // acquire: TMA data visible
        ph[bq] ^= 1;

        float* __restrict__ sb = stage[bq];
        float r[64];

        // ---- Pass A: transform bits {6..11}. Thread owns i = t | m<<6. ----
        // strided scalar reads from linear buffer, conflict-free; sign-XOR.
#pragma unroll
        for (int m = 0; m < 64; m++) {
            const unsigned bit = (m < 32) ? (sm0 >> m) : (sm1 >> (m - 32));
            r[m] = __uint_as_float(__float_as_uint(sb[t + (m << 6)]) ^
                                   ((bit & 1u) << 31));
        }
        fwht64p(r);
        __syncthreads();   // all raw reads done before in-place swizzled writes

        // ---- remap: in-place swizzled writes ----
#pragma unroll
        for (int m = 0; m < 64; m++) {
            sb[t ^ (m << 6) ^ ((m & 31) << 2)] = r[m];
        }
        __syncthreads();

        // ---- Pass C: transform bits {0..5}. Thread owns i = w | t<<6. ----
        {
            const float4* __restrict__ sp4 = reinterpret_cast<const float4*>(sb);
            const int cb = (t << 4) ^ (t & 31);
#pragma unroll
            for (int q = 0; q < 16; q++) {
                float4 v = sp4[q ^ cb];
                r[4 * q + 0] = v.x; r[4 * q + 1] = v.y;
                r[4 * q + 2] = v.z; r[4 * q + 3] = v.w;
            }
        }
        fwht64p(r);
#pragma unroll
        for (int p = 0; p < 32; p++) scale2(r[2 * p], r[2 * p + 1], 0.015625f);

        // ---- stores: float4 at out[row*D + (t<<6) + 4q] ----
        {
            float4* __restrict__ o4 =
                reinterpret_cast<float4*>(out + (size_t)row * D) + (t << 4);
#pragma unroll
            for (int q = 0; q < 16; q++) {
                __stcs(o4 + q, make_float4(r[4 * q + 0], r[4 * q + 1],
                                           r[4 * q + 2], r[4 * q + 3]));
            }
        }

        __syncthreads();   // all pass-C reads of buf bq done before refill

        const int row2 = row + 2 * stride;
        if (t == 0 && row2 < n_rows) {
            mbar_expect_tx(mb32[bq], ROW_BYTES);
            bulk_g2s(st32[bq], x + (size_t)row2 * D, ROW_BYTES, mb32[bq]);
        }

        row += stride;
        bq ^= 1;
    }
}

extern "C" void kernel_launch(void* const* d_in, const int* in_sizes, int n_in,
                              void* d_out, int out_size) {
    const float* x     = (const float*)d_in[0];
    const float* signs = (const float*)d_in[1];
    float* out = (float*)d_out;

    const int n_rows = in_sizes[0] / D;  // 8192

    int sm_count = 152;
    cudaDeviceGetAttribute(&sm_count, cudaDevAttrMultiProcessorCount, 0);
    int grid = sm_count * OCC;
    if (grid > n_rows) grid = n_rows;

    rht_kernel<<<grid, T>>>(x, signs, out, n_rows, grid);
}

// round 11
// speedup vs baseline: 1.1945x; 1.1945x over previous
#include <cuda_runtime.h>
#include <cuda_bf16.h>

#define D 4096
#define THREADS 256
#define NCTAS 608   // 152 SMs x 4 CTAs: one persistent wave

// Bank swizzle: phys = i ^ g(i), g = (i>>4) & 0x1C   (i6->b2, i7->b3, i8->b4)
// Conflict-free (rank-5 injective bank maps) for all shared patterns below
// (verified R6). g never touches bits [1:0] => float4 groups stay aligned.
__device__ __forceinline__ int swz(int i) {
    return i ^ ((i >> 4) & 0x1C);
}

// Packed butterfly via f32x2: 2 butterflies in 2 instructions.
__device__ __forceinline__ void bfly2(float& a0, float& a1, float& b0, float& b1) {
    asm("{\n\t"
        ".reg .b32 m;\n\t"
        ".reg .b64 ra, rb, rs, rd, rn;\n\t"
        "mov.b32 m, 0xBF800000;\n\t"
        "mov.b64 rn, {m, m};\n\t"
        "mov.b64 ra, {%0, %1};\n\t"
        "mov.b64 rb, {%2, %3};\n\t"
        "add.rn.f32x2 rs, ra, rb;\n\t"
        "fma.rn.f32x2 rd, rb, rn, ra;\n\t"
        "mov.b64 {%0, %1}, rs;\n\t"
        "mov.b64 {%2, %3}, rd;\n\t"
        "}" : "+f"(a0), "+f"(a1), "+f"(b0), "+f"(b1));
}

// Packed multiply: (a0,a1) *= (s0,s1)
__device__ __forceinline__ void mul2(float& a0, float& a1, float s0, float s1) {
    asm("{\n\t"
        ".reg .b64 ra, rs, rm;\n\t"
        "mov.b64 ra, {%0, %1};\n\t"
        "mov.b64 rs, {%2, %3};\n\t"
        "mul.rn.f32x2 rm, ra, rs;\n\t"
        "mov.b64 {%0, %1}, rm;\n\t"
        "}" : "+f"(a0), "+f"(a1) : "f"(s0), "f"(s1));
}

// 16-point FWHT: reg bits 1..3 packed (pairs along bit 0), bit 0 scalar.
__device__ __forceinline__ void fwht16p(float r[16]) {
#pragma unroll
    for (int hp = 1; hp < 8; hp <<= 1) {
#pragma unroll
        for (int m = 0; m < 8; m++) {
            if (!(m & hp)) {
                bfly2(r[2 * m], r[2 * m + 1],
                      r[2 * (m | hp)], r[2 * (m | hp) + 1]);
            }
        }
    }
#pragma unroll
    for (int m = 0; m < 8; m++) {
        float a = r[2 * m], b = r[2 * m + 1];
        r[2 * m]     = a + b;
        r[2 * m + 1] = a - b;
    }
}

__global__ __launch_bounds__(THREADS, 4)
void rht_kernel(const float* __restrict__ x,
                const float* __restrict__ signs,
                float* __restrict__ out,
                int n_rows) {
    __shared__ float s[2][D];

    const int t = threadIdx.x;

    const int f4w   = t ^ ((t >> 4) & 7);             // pass-1 STS.128 index
    const int base2 = ((t >> 2) << 6) | (t & 3);
    const int sb2   = swz(base2);
    const int base3 = ((t >> 6) << 10) | (t & 63);    // bits 6..9 zero -> swz=id

    // signs: row-invariant -> registers, pre-scaled by D^-1/2 = 1/64
    const float4* __restrict__ sv4 = reinterpret_cast<const float4*>(signs);
    float4 sv[4];
#pragma unroll
    for (int h = 0; h < 4; h++) {
        float4 v = sv4[(h << 8) + t];
        v.x *= 0.015625f; v.y *= 0.015625f; v.z *= 0.015625f; v.w *= 0.015625f;
        sv[h] = v;
    }

    // prefetch first row (streaming load: zero reuse, keep L2 for the stream)
    int row = blockIdx.x;
    float4 xa[4];
    {
        const float4* __restrict__ xv4 =
            reinterpret_cast<const float4*>(x + (size_t)row * D);
#pragma unroll
        for (int h = 0; h < 4; h++) xa[h] = __ldcs(xv4 + (h << 8) + t);
    }

    int buf = 0;
    while (row < n_rows) {
        float r[16];

        // ---- Pass A: bits {0,1,10,11} (reg: j->i{0,1}, h->i{10,11}) ----
#pragma unroll
        for (int h = 0; h < 4; h++) {
            r[h * 4 + 0] = xa[h].x; r[h * 4 + 1] = xa[h].y;
            r[h * 4 + 2] = xa[h].z; r[h * 4 + 3] = xa[h].w;
            mul2(r[h * 4 + 0], r[h * 4 + 1], sv[h].x, sv[h].y);
            mul2(r[h * 4 + 2], r[h * 4 + 3], sv[h].z, sv[h].w);
        }
        fwht16p(r);

        // ---- remap 1: 4x STS.128 at i = (h<<10)|(t<<2)|j ----
        {
            float4* __restrict__ s4 = reinterpret_cast<float4*>(s[buf]);
#pragma unroll
            for (int h = 0; h < 4; h++) {
                s4[(h << 8) + f4w] =
                    make_float4(r[h * 4 + 0], r[h * 4 + 1],
                                r[h * 4 + 2], r[h * 4 + 3]);
            }
        }

        // ---- prefetch next row (overlaps barrier + passes B/C) ----
        const int nrow = row + NCTAS;
        {
            const int prow = (nrow < n_rows) ? nrow : row;  // safe clamp
            const float4* __restrict__ xv4 =
                reinterpret_cast<const float4*>(x + (size_t)prow * D);
#pragma unroll
            for (int h = 0; h < 4; h++) xa[h] = __ldcs(xv4 + (h << 8) + t);
        }

        __syncthreads();

        // ---- Pass B: bits {2,3,4,5} (reg k -> i{2..5}) ----
#pragma unroll
        for (int k = 0; k < 16; k++) {
            r[k] = s[buf][sb2 ^ (k << 2)];
        }
        fwht16p(r);
#pragma unroll
        for (int k = 0; k < 16; k++) {
            s[buf][sb2 ^ (k << 2)] = r[k];
        }
        __syncthreads();

        // ---- Pass C: bits {6,7,8,9} (reg k -> i{6..9}) ----
#pragma unroll
        for (int k = 0; k < 16; k++) {
            r[k] = s[buf][base3 ^ (k << 6) ^ ((k & 7) << 2)];
        }
        fwht16p(r);

        // ---- streaming coalesced stores at logical i = base3 + k*64 ----
        // evict-first stores: don't let the write stream thrash the read
        // stream out of L2 (126MB L2 vs 256MB total streamed).
        float* __restrict__ orow = out + (size_t)row * D;
#pragma unroll
        for (int k = 0; k < 16; k++) {
            __stcs(&orow[base3 + (k << 6)], r[k]);
        }

        row = nrow;
        buf ^= 1;
    }
}

extern "C" void kernel_launch(void* const* d_in, const int* in_sizes, int n_in,
                              void* d_out, int out_size) {
    const float* x     = (const float*)d_in[0];
    const float* signs = (const float*)d_in[1];
    float* out = (float*)d_out;

    const int n_rows = in_sizes[0] / D;  // 8192
    const int grid = (n_rows < NCTAS) ? n_rows : NCTAS;
    rht_kernel<<<grid, THREADS>>>(x, signs, out, n_rows);
}